// round 16
// baseline (speedup 1.0000x reference)
#include <cuda_runtime.h>
#include <cuda_bf16.h>
#include <cuda_fp16.h>
#include <cuda_pipeline.h>
#include <mma.h>
#include <math.h>

using namespace nvcuda;

constexpr int kEmbed   = 1024;
constexpr int kHeads   = 16;
constexpr int kHeadDim = 64;
constexpr int kSeq     = 2048;
constexpr int kBatch   = 4;
constexpr int kQkvN    = 3 * kEmbed;          // 3072
constexpr int kRows    = kBatch * kSeq;       // 8192
constexpr int kBHT     = kBatch * kHeads * kSeq * kHeadDim;

// q pre-scale: 1/sqrt(64) * log2(e)  (softmax exp becomes exp2)
constexpr float kQScale = 0.125f * 1.4426950408889634f;

// -------- scratch (static device globals; no runtime allocation) --------
__device__ __align__(128) __half g_x[kRows * kEmbed];      // x single fp16
__device__ __align__(128) __half g_wqkv[kEmbed * kQkvN];   // weights single fp16
__device__ __align__(128) float g_bqkv[kQkvN];
// attention operands, all single fp16 (q pre-scaled by kQScale)
__device__ __align__(128) __half g_q[kBHT];
__device__ __align__(128) __half g_k[kBHT];
__device__ __align__(128) __half g_v[kBHT];
__device__ __align__(128) __half g_at[kRows * kEmbed];     // att single fp16
__device__ __align__(128) __half g_wp[kEmbed * kEmbed];    // single fp16

// ======================= fused conversion / packing =======================
constexpr int kCvt1 = kRows * kEmbed / 4;          // x, float4 granular
constexpr int kCvt2 = kCvt1 + kEmbed * kEmbed / 4; // Wp, float4 granular
constexpr int kCvt3 = kCvt2 + kEmbed * kQkvN;      // Wqkv gather + bias

__global__ void pack_all_kernel(const float* __restrict__ x, const float* __restrict__ Wp,
                                const float* __restrict__ Wq, const float* __restrict__ Wk,
                                const float* __restrict__ Wv, const float* __restrict__ bq,
                                const float* __restrict__ bk, const float* __restrict__ bv) {
    int idx = blockIdx.x * blockDim.x + threadIdx.x;
    if (idx < kCvt1) {
        float4 v = ((const float4*)x)[idx];
        ((__half2*)g_x)[2 * idx]     = __floats2half2_rn(v.x, v.y);
        ((__half2*)g_x)[2 * idx + 1] = __floats2half2_rn(v.z, v.w);
    } else if (idx < kCvt2) {
        const int i = idx - kCvt1;
        float4 v = ((const float4*)Wp)[i];
        ((__half2*)g_wp)[2 * i]     = __floats2half2_rn(v.x, v.y);
        ((__half2*)g_wp)[2 * i + 1] = __floats2half2_rn(v.z, v.w);
    } else if (idx < kCvt3) {
        const int i = idx - kCvt2;
        const int e = i / kQkvN;
        const int n = i % kQkvN;
        const int which = n >> 10;
        const int hd    = n & 1023;
        const int h = hd >> 6, d = hd & 63;
        const float* W = (which == 0) ? Wq : (which == 1) ? Wk : Wv;
        g_wqkv[i] = __float2half(W[((size_t)h * kEmbed + e) * kHeadDim + d]);
        if (i < kQkvN) {
            const int wh = i >> 10, bhd = i & 1023;
            const float* bb = (wh == 0) ? bq : (wh == 1) ? bk : bv;
            g_bqkv[i] = bb[bhd];
        }
    }
}

// ======================= fp16 WMMA GEMM =======================
// acc += A*B (single fp16, fp32 accumulate). Block 128x128, BK=32,
// cp.async 3-stage, 128 threads / 4 warps (2m x 2n), warp tile 64x64, 2 CTAs/SM.
constexpr int kGA = 0;                       // [128][40] half = 10240
constexpr int kGB = 10240;                   // [32][136] half = 8704
constexpr int kGStage = 18944;
constexpr int kGemmSmem = 3 * kGStage;       // 56832

__global__ __launch_bounds__(128, 2)
void gemm_wmma_kernel(const float* __restrict__ bias_arg, float* __restrict__ outp, int mode) {
    extern __shared__ char sm[];

    const int N = (mode == 0) ? kQkvN : kEmbed;
    const __half* A = (mode == 0) ? g_x : g_at;
    const __half* B = (mode == 0) ? g_wqkv : g_wp;
    const float* bias = (mode == 0) ? g_bqkv : bias_arg;

    const int tid  = threadIdx.x;
    const int warp = tid >> 5, lane = tid & 31;
    const int wm   = warp >> 1, wn = warp & 1;   // 2 x 2 warp grid
    const int bm   = blockIdx.y * 128;
    const int bn   = blockIdx.x * 128;

    auto loadStage = [&](int kt, int s) {
        const int k0 = kt * 32;
        char* st = sm + s * kGStage;
        __half* sA = (__half*)(st + kGA);
        __half* sB = (__half*)(st + kGB);
#pragma unroll
        for (int i = 0; i < 4; i++) {
            const int idx = i * 128 + tid;
            const int ar = idx >> 2, ac = (idx & 3) * 8;
            const size_t asrc = (size_t)(bm + ar) * kEmbed + k0 + ac;
            __pipeline_memcpy_async(sA + ar * 40 + ac, A + asrc, 16);
            const int br = idx >> 4, bc = (idx & 15) * 8;
            const size_t bsrc = (size_t)(k0 + br) * N + bn + bc;
            __pipeline_memcpy_async(sB + br * 136 + bc, B + bsrc, 16);
        }
        __pipeline_commit();
    };

    wmma::fragment<wmma::accumulator, 16, 16, 16, float> acc[4][4];
#pragma unroll
    for (int mi = 0; mi < 4; mi++)
#pragma unroll
        for (int ni = 0; ni < 4; ni++) wmma::fill_fragment(acc[mi][ni], 0.0f);

    constexpr int NT = kEmbed / 32;
    loadStage(0, 0);
    loadStage(1, 1);

    for (int kt = 0; kt < NT; kt++) {
        if (kt < NT - 2) __pipeline_wait_prior(1);
        else             __pipeline_wait_prior(0);
        __syncthreads();
        if (kt + 2 < NT) loadStage(kt + 2, (kt + 2) % 3);

        char* st = sm + (kt % 3) * kGStage;
        const __half* sA = (const __half*)(st + kGA);
        const __half* sB = (const __half*)(st + kGB);

#pragma unroll
        for (int kk = 0; kk < 2; kk++) {
            wmma::fragment<wmma::matrix_a, 16, 16, 16, __half, wmma::row_major> fa[4];
            wmma::fragment<wmma::matrix_b, 16, 16, 16, __half, wmma::row_major> fb[4];
#pragma unroll
            for (int mi = 0; mi < 4; mi++)
                wmma::load_matrix_sync(fa[mi], sA + (wm * 64 + mi * 16) * 40 + kk * 16, 40);
#pragma unroll
            for (int ni = 0; ni < 4; ni++)
                wmma::load_matrix_sync(fb[ni], sB + (kk * 16) * 136 + wn * 64 + ni * 16, 136);
#pragma unroll
            for (int mi = 0; mi < 4; mi++)
#pragma unroll
                for (int ni = 0; ni < 4; ni++)
                    wmma::mma_sync(acc[mi][ni], fa[mi], fb[ni], acc[mi][ni]);
        }
    }

    // direct fragment epilogue (sm_80+ accumulator layout)
#pragma unroll
    for (int mi = 0; mi < 4; mi++) {
#pragma unroll
        for (int ni = 0; ni < 4; ni++) {
#pragma unroll
            for (int i2 = 0; i2 < 4; i2++) {
                const int i = 2 * i2;
                const int row = bm + wm * 64 + mi * 16 + (lane >> 2) + ((i & 2) ? 8 : 0);
                const int col = bn + wn * 64 + ni * 16 + (lane & 3) * 2 + ((i & 4) ? 8 : 0);
                float v0 = acc[mi][ni].x[i]     + bias[col];
                float v1 = acc[mi][ni].x[i + 1] + bias[col + 1];
                if (mode == 0) {
                    const int which = col >> 10, hd = col & 1023;
                    const int h = hd >> 6, d = hd & 63;
                    const int b = row >> 11, t = row & 2047;
                    const size_t o = (((size_t)(b * kHeads + h) * kSeq) + t) * kHeadDim + d;
                    if (which == 0) { v0 *= kQScale; v1 *= kQScale; }
                    __half* dst = (which == 0) ? g_q : ((which == 1) ? g_k : g_v);
                    *(__half2*)(dst + o) = __floats2half2_rn(v0, v1);
                } else {
                    float2 vv; vv.x = v0; vv.y = v1;
                    *(float2*)(outp + (size_t)row * kEmbed + col) = vv;
                }
            }
        }
    }
}

// ======================= fp16 WMMA causal attention =======================
// 256 threads, 256 q-rows/CTA (warp owns 32 = 2 row-blocks), kv tile 64,
// cp.async double buffer. K/V fragments reused across both row-blocks
// (MMA:LDSM = 2:1). Softmax in registers -> matrix_a fragment directly.
constexpr int kKVBuf  = 2 * 9216;            // k, v each half[64][72]
constexpr int kAttnSmem = 2 * kKVBuf;        // 36864

__global__ __launch_bounds__(256, 1)
void attn_wmma_kernel() {
    extern __shared__ char sm[];

    const int qi  = gridDim.x - 1 - blockIdx.x;   // big tiles first
    const int bh  = blockIdx.y;
    const int tid = threadIdx.x;
    const int warp = tid >> 5, lane = tid & 31;
    const int q0  = qi * 256;
    const size_t base = (size_t)bh * kSeq * kHeadDim;

    auto loadKV = [&](int kt, int b) {
        const int k0 = kt * 64;
        char* kv = sm + b * kKVBuf;
        __half* skh = (__half*)(kv);
        __half* svh = (__half*)(kv + 9216);
#pragma unroll
        for (int i = 0; i < 2; i++) {
            const int idx = i * 256 + tid;
            const int r = idx >> 3, c8 = (idx & 7) * 8;
            const size_t g = base + (size_t)(k0 + r) * kHeadDim + c8;
            const int so = r * 72 + c8;
            __pipeline_memcpy_async(skh + so, g_k + g, 16);
            __pipeline_memcpy_async(svh + so, g_v + g, 16);
        }
        __pipeline_commit();
    };

    // Q fragments: 2 row-blocks x 4 k-chunks
    wmma::fragment<wmma::matrix_a, 16, 16, 16, __half, wmma::row_major> fq[2][4];
#pragma unroll
    for (int rb = 0; rb < 2; rb++)
#pragma unroll
        for (int kk = 0; kk < 4; kk++) {
            const size_t qo = base + (size_t)(q0 + warp * 32 + rb * 16) * kHeadDim + kk * 16;
            wmma::load_matrix_sync(fq[rb][kk], g_q + qo, kHeadDim);
        }

    wmma::fragment<wmma::accumulator, 16, 16, 16, float> oacc[2][4];
#pragma unroll
    for (int rb = 0; rb < 2; rb++)
#pragma unroll
        for (int d4 = 0; d4 < 4; d4++) wmma::fill_fragment(oacc[rb][d4], 0.0f);

    const int rlow = (lane >> 2);
    float lacc[2][2] = {{0.f, 0.f}, {0.f, 0.f}};   // [rb][half-of-rows]

    const int ntiles = 4 * qi + 4;
    loadKV(0, 0);

    for (int kt = 0; kt < ntiles; kt++) {
        const int k0  = kt * 64;
        const int buf = kt & 1;
        const bool needMask = (kt >= 4 * qi);   // last 4 tiles touch the diagonal
        char* kv = sm + buf * kKVBuf;
        const __half* skh = (const __half*)(kv);
        const __half* svh = (const __half*)(kv + 9216);

        __pipeline_wait_prior(0);
        __syncthreads();
        if (kt + 1 < ntiles) loadKV(kt + 1, buf ^ 1);

#pragma unroll
        for (int nt4 = 0; nt4 < 4; nt4++) {
            wmma::fragment<wmma::accumulator, 16, 16, 16, float> sacc[2];
            wmma::fill_fragment(sacc[0], 0.0f);
            wmma::fill_fragment(sacc[1], 0.0f);
#pragma unroll
            for (int kk = 0; kk < 4; kk++) {
                wmma::fragment<wmma::matrix_b, 16, 16, 16, __half, wmma::col_major> fbh;
                wmma::load_matrix_sync(fbh, skh + (nt4 * 16) * 72 + kk * 16, 72);
                wmma::mma_sync(sacc[0], fq[0][kk], fbh, sacc[0]);
                wmma::mma_sync(sacc[1], fq[1][kk], fbh, sacc[1]);
            }

            wmma::fragment<wmma::matrix_a, 16, 16, 16, __half, wmma::row_major> fp[2];
#pragma unroll
            for (int rb = 0; rb < 2; rb++) {
#pragma unroll
                for (int i2 = 0; i2 < 4; i2++) {
                    const int i = 2 * i2;
                    float s0 = sacc[rb].x[i], s1 = sacc[rb].x[i + 1];
                    if (needMask) {
                        const int qg = q0 + warp * 32 + rb * 16 + rlow + ((i & 2) ? 8 : 0);
                        const int kg = k0 + nt4 * 16 + (lane & 3) * 2 + ((i & 4) ? 8 : 0);
                        if (kg     > qg) s0 = -INFINITY;
                        if (kg + 1 > qg) s1 = -INFINITY;
                    }
                    const __half2 hp = h2exp2(__floats2half2_rn(s0, s1));
                    fp[rb].x[i]     = __low2half(hp);
                    fp[rb].x[i + 1] = __high2half(hp);
                    const float2 lf = __half22float2(hp);
                    lacc[rb][(i & 2) ? 1 : 0] += lf.x + lf.y;
                }
            }

#pragma unroll
            for (int d4 = 0; d4 < 4; d4++) {
                wmma::fragment<wmma::matrix_b, 16, 16, 16, __half, wmma::row_major> fvh;
                wmma::load_matrix_sync(fvh, svh + (nt4 * 16) * 72 + d4 * 16, 72);
                wmma::mma_sync(oacc[0][d4], fp[0], fvh, oacc[0][d4]);
                wmma::mma_sync(oacc[1][d4], fp[1], fvh, oacc[1][d4]);
            }
        }
    }

    // row-sum reduce across the 4 lanes sharing each row
    float inv[2][2];
#pragma unroll
    for (int rb = 0; rb < 2; rb++)
#pragma unroll
        for (int hf = 0; hf < 2; hf++) {
            float l = lacc[rb][hf];
            l += __shfl_xor_sync(0xffffffffu, l, 1);
            l += __shfl_xor_sync(0xffffffffu, l, 2);
            inv[rb][hf] = 1.f / l;
        }

    const int b = bh >> 4, h = bh & 15;
#pragma unroll
    for (int rb = 0; rb < 2; rb++) {
#pragma unroll
        for (int d4 = 0; d4 < 4; d4++) {
#pragma unroll
            for (int i2 = 0; i2 < 4; i2++) {
                const int i = 2 * i2;
                const int qg = q0 + warp * 32 + rb * 16 + rlow + ((i & 2) ? 8 : 0);
                const float iv = inv[rb][(i & 2) ? 1 : 0];
                const int colb = d4 * 16 + (lane & 3) * 2 + ((i & 4) ? 8 : 0);
                const float v0 = oacc[rb][d4].x[i]     * iv;
                const float v1 = oacc[rb][d4].x[i + 1] * iv;
                const size_t o = ((size_t)(b * kSeq + qg)) * kEmbed + h * kHeadDim + colb;
                *(__half2*)(g_at + o) = __floats2half2_rn(v0, v1);
            }
        }
    }
}

// ======================= launch =======================
extern "C" void kernel_launch(void* const* d_in, const int* in_sizes, int n_in,
                              void* d_out, int out_size) {
    const float* x  = (const float*)d_in[0];
    const float* Wq = (const float*)d_in[1];
    const float* Wk = (const float*)d_in[2];
    const float* Wv = (const float*)d_in[3];
    const float* bq = (const float*)d_in[4];
    const float* bk = (const float*)d_in[5];
    const float* bv = (const float*)d_in[6];
    const float* Wp = (const float*)d_in[7];
    const float* bp = (const float*)d_in[8];
    float* out = (float*)d_out;

    cudaFuncSetAttribute(gemm_wmma_kernel, cudaFuncAttributeMaxDynamicSharedMemorySize, kGemmSmem);
    cudaFuncSetAttribute(attn_wmma_kernel, cudaFuncAttributeMaxDynamicSharedMemorySize, kAttnSmem);

    // fused input/weight conversion + packing
    pack_all_kernel<<<(kCvt3 + 255) / 256, 256>>>(x, Wp, Wq, Wk, Wv, bq, bk, bv);

    // QKV projection: [8192,1024] x [1024,3072] -> fp16 q/k/v
    gemm_wmma_kernel<<<dim3(kQkvN / 128, kRows / 128), 128, kGemmSmem>>>(nullptr, nullptr, 0);

    // causal attention on tensor cores (256 q-rows per CTA)
    attn_wmma_kernel<<<dim3(kSeq / 256, kBatch * kHeads), 256, kAttnSmem>>>();

    // output projection: [8192,1024] x [1024,1024] + bias
    gemm_wmma_kernel<<<dim3(kEmbed / 128, kRows / 128), 128, kGemmSmem>>>(bp, out, 1);
}

// round 17
// speedup vs baseline: 1.0119x; 1.0119x over previous
#include <cuda_runtime.h>
#include <cuda_bf16.h>
#include <cuda_fp16.h>
#include <cuda_pipeline.h>
#include <mma.h>
#include <math.h>

using namespace nvcuda;

constexpr int kEmbed   = 1024;
constexpr int kHeads   = 16;
constexpr int kHeadDim = 64;
constexpr int kSeq     = 2048;
constexpr int kBatch   = 4;
constexpr int kQkvN    = 3 * kEmbed;          // 3072
constexpr int kRows    = kBatch * kSeq;       // 8192
constexpr int kBHT     = kBatch * kHeads * kSeq * kHeadDim;

// q pre-scale: 1/sqrt(64) * log2(e)  (softmax exp becomes exp2)
constexpr float kQScale = 0.125f * 1.4426950408889634f;

// -------- scratch (static device globals; no runtime allocation) --------
__device__ __align__(128) __half g_x[kRows * kEmbed];      // x single fp16
__device__ __align__(128) __half g_wqkv[kEmbed * kQkvN];   // weights single fp16
__device__ __align__(128) float g_bqkv[kQkvN];
// attention operands, all single fp16 (q pre-scaled by kQScale)
__device__ __align__(128) __half g_q[kBHT];
__device__ __align__(128) __half g_k[kBHT];
__device__ __align__(128) __half g_v[kBHT];
__device__ __align__(128) __half g_at[kRows * kEmbed];     // att single fp16
__device__ __align__(128) __half g_wp[kEmbed * kEmbed];    // single fp16

// ======================= fused conversion / packing =======================
constexpr int kCvt1 = kRows * kEmbed / 4;          // x, float4 granular
constexpr int kCvt2 = kCvt1 + kEmbed * kEmbed / 4; // Wp, float4 granular
constexpr int kCvt3 = kCvt2 + kEmbed * kQkvN;      // Wqkv gather + bias

__global__ void pack_all_kernel(const float* __restrict__ x, const float* __restrict__ Wp,
                                const float* __restrict__ Wq, const float* __restrict__ Wk,
                                const float* __restrict__ Wv, const float* __restrict__ bq,
                                const float* __restrict__ bk, const float* __restrict__ bv) {
    int idx = blockIdx.x * blockDim.x + threadIdx.x;
    if (idx < kCvt1) {
        float4 v = ((const float4*)x)[idx];
        ((__half2*)g_x)[2 * idx]     = __floats2half2_rn(v.x, v.y);
        ((__half2*)g_x)[2 * idx + 1] = __floats2half2_rn(v.z, v.w);
    } else if (idx < kCvt2) {
        const int i = idx - kCvt1;
        float4 v = ((const float4*)Wp)[i];
        ((__half2*)g_wp)[2 * i]     = __floats2half2_rn(v.x, v.y);
        ((__half2*)g_wp)[2 * i + 1] = __floats2half2_rn(v.z, v.w);
    } else if (idx < kCvt3) {
        const int i = idx - kCvt2;
        const int e = i / kQkvN;
        const int n = i % kQkvN;
        const int which = n >> 10;
        const int hd    = n & 1023;
        const int h = hd >> 6, d = hd & 63;
        const float* W = (which == 0) ? Wq : (which == 1) ? Wk : Wv;
        g_wqkv[i] = __float2half(W[((size_t)h * kEmbed + e) * kHeadDim + d]);
        if (i < kQkvN) {
            const int wh = i >> 10, bhd = i & 1023;
            const float* bb = (wh == 0) ? bq : (wh == 1) ? bk : bv;
            g_bqkv[i] = bb[bhd];
        }
    }
}

// ======================= fp16 WMMA GEMM =======================
// acc += A*B (single fp16, fp32 accumulate). Block 128x128, BK=32,
// cp.async 3-stage, 128 threads / 4 warps (2m x 2n), warp tile 64x64, 2 CTAs/SM.
constexpr int kGA = 0;                       // [128][40] half = 10240
constexpr int kGB = 10240;                   // [32][136] half = 8704
constexpr int kGStage = 18944;
constexpr int kGemmSmem = 3 * kGStage;       // 56832

__global__ __launch_bounds__(128, 2)
void gemm_wmma_kernel(const float* __restrict__ bias_arg, float* __restrict__ outp, int mode) {
    extern __shared__ char sm[];

    const int N = (mode == 0) ? kQkvN : kEmbed;
    const __half* A = (mode == 0) ? g_x : g_at;
    const __half* B = (mode == 0) ? g_wqkv : g_wp;
    const float* bias = (mode == 0) ? g_bqkv : bias_arg;

    const int tid  = threadIdx.x;
    const int warp = tid >> 5, lane = tid & 31;
    const int wm   = warp >> 1, wn = warp & 1;   // 2 x 2 warp grid
    const int bm   = blockIdx.y * 128;
    const int bn   = blockIdx.x * 128;

    auto loadStage = [&](int kt, int s) {
        const int k0 = kt * 32;
        char* st = sm + s * kGStage;
        __half* sA = (__half*)(st + kGA);
        __half* sB = (__half*)(st + kGB);
#pragma unroll
        for (int i = 0; i < 4; i++) {
            const int idx = i * 128 + tid;
            const int ar = idx >> 2, ac = (idx & 3) * 8;
            const size_t asrc = (size_t)(bm + ar) * kEmbed + k0 + ac;
            __pipeline_memcpy_async(sA + ar * 40 + ac, A + asrc, 16);
            const int br = idx >> 4, bc = (idx & 15) * 8;
            const size_t bsrc = (size_t)(k0 + br) * N + bn + bc;
            __pipeline_memcpy_async(sB + br * 136 + bc, B + bsrc, 16);
        }
        __pipeline_commit();
    };

    wmma::fragment<wmma::accumulator, 16, 16, 16, float> acc[4][4];
#pragma unroll
    for (int mi = 0; mi < 4; mi++)
#pragma unroll
        for (int ni = 0; ni < 4; ni++) wmma::fill_fragment(acc[mi][ni], 0.0f);

    constexpr int NT = kEmbed / 32;
    loadStage(0, 0);
    loadStage(1, 1);

    for (int kt = 0; kt < NT; kt++) {
        if (kt < NT - 2) __pipeline_wait_prior(1);
        else             __pipeline_wait_prior(0);
        __syncthreads();
        if (kt + 2 < NT) loadStage(kt + 2, (kt + 2) % 3);

        char* st = sm + (kt % 3) * kGStage;
        const __half* sA = (const __half*)(st + kGA);
        const __half* sB = (const __half*)(st + kGB);

#pragma unroll
        for (int kk = 0; kk < 2; kk++) {
            wmma::fragment<wmma::matrix_a, 16, 16, 16, __half, wmma::row_major> fa[4];
            wmma::fragment<wmma::matrix_b, 16, 16, 16, __half, wmma::row_major> fb[4];
#pragma unroll
            for (int mi = 0; mi < 4; mi++)
                wmma::load_matrix_sync(fa[mi], sA + (wm * 64 + mi * 16) * 40 + kk * 16, 40);
#pragma unroll
            for (int ni = 0; ni < 4; ni++)
                wmma::load_matrix_sync(fb[ni], sB + (kk * 16) * 136 + wn * 64 + ni * 16, 136);
#pragma unroll
            for (int mi = 0; mi < 4; mi++)
#pragma unroll
                for (int ni = 0; ni < 4; ni++)
                    wmma::mma_sync(acc[mi][ni], fa[mi], fb[ni], acc[mi][ni]);
        }
    }

    // direct fragment epilogue (sm_80+ accumulator layout)
#pragma unroll
    for (int mi = 0; mi < 4; mi++) {
#pragma unroll
        for (int ni = 0; ni < 4; ni++) {
#pragma unroll
            for (int i2 = 0; i2 < 4; i2++) {
                const int i = 2 * i2;
                const int row = bm + wm * 64 + mi * 16 + (lane >> 2) + ((i & 2) ? 8 : 0);
                const int col = bn + wn * 64 + ni * 16 + (lane & 3) * 2 + ((i & 4) ? 8 : 0);
                float v0 = acc[mi][ni].x[i]     + bias[col];
                float v1 = acc[mi][ni].x[i + 1] + bias[col + 1];
                if (mode == 0) {
                    const int which = col >> 10, hd = col & 1023;
                    const int h = hd >> 6, d = hd & 63;
                    const int b = row >> 11, t = row & 2047;
                    const size_t o = (((size_t)(b * kHeads + h) * kSeq) + t) * kHeadDim + d;
                    if (which == 0) { v0 *= kQScale; v1 *= kQScale; }
                    __half* dst = (which == 0) ? g_q : ((which == 1) ? g_k : g_v);
                    *(__half2*)(dst + o) = __floats2half2_rn(v0, v1);
                } else {
                    float2 vv; vv.x = v0; vv.y = v1;
                    *(float2*)(outp + (size_t)row * kEmbed + col) = vv;
                }
            }
        }
    }
}

// ======================= fp16 WMMA causal attention =======================
// 256 threads, 128 q-rows/CTA (warp owns 16), kv tile 64, cp.async THREE-stage
// (KV stream is L2-resident; 2 tiles in flight hides L2 latency at each sync).
// S = q*k (1 MMA), p = h2exp2(S) in-register -> matrix_a fragment, O += p*v.
constexpr int kKVStage = 2 * 9216;           // k, v each half[64][72]
constexpr int kAttnSmem = 3 * kKVStage;      // 55296

__global__ __launch_bounds__(256, 2)
void attn_wmma_kernel() {
    extern __shared__ char sm[];

    const int qi  = gridDim.x - 1 - blockIdx.x;   // big tiles first
    const int bh  = blockIdx.y;
    const int tid = threadIdx.x;
    const int warp = tid >> 5, lane = tid & 31;
    const int q0  = qi * 128;
    const size_t base = (size_t)bh * kSeq * kHeadDim;

    auto loadKV = [&](int kt, int b) {
        const int k0 = kt * 64;
        char* kv = sm + b * kKVStage;
        __half* skh = (__half*)(kv);
        __half* svh = (__half*)(kv + 9216);
#pragma unroll
        for (int i = 0; i < 2; i++) {
            const int idx = i * 256 + tid;
            const int r = idx >> 3, c8 = (idx & 7) * 8;
            const size_t g = base + (size_t)(k0 + r) * kHeadDim + c8;
            const int so = r * 72 + c8;
            __pipeline_memcpy_async(skh + so, g_k + g, 16);
            __pipeline_memcpy_async(svh + so, g_v + g, 16);
        }
        __pipeline_commit();
    };

    wmma::fragment<wmma::matrix_a, 16, 16, 16, __half, wmma::row_major> fq[4];
#pragma unroll
    for (int kk = 0; kk < 4; kk++) {
        const size_t qo = base + (size_t)(q0 + warp * 16) * kHeadDim + kk * 16;
        wmma::load_matrix_sync(fq[kk], g_q + qo, kHeadDim);
    }

    wmma::fragment<wmma::accumulator, 16, 16, 16, float> oacc[4];
#pragma unroll
    for (int d4 = 0; d4 < 4; d4++) wmma::fill_fragment(oacc[d4], 0.0f);

    const int rlow  = warp * 16 + (lane >> 2);
    const int qglow = q0 + rlow;
    float lacc0 = 0.f, lacc1 = 0.f;

    const int ntiles = 2 * qi + 2;
    loadKV(0, 0);
    if (ntiles > 1) loadKV(1, 1);

    for (int kt = 0; kt < ntiles; kt++) {
        const int k0  = kt * 64;
        const int buf = kt % 3;
        const bool needMask = (kt >= 2 * qi);   // only last two tiles touch the diagonal
        char* kv = sm + buf * kKVStage;
        const __half* skh = (const __half*)(kv);
        const __half* svh = (const __half*)(kv + 9216);

        if (kt + 1 < ntiles) __pipeline_wait_prior(1);
        else                 __pipeline_wait_prior(0);
        __syncthreads();
        if (kt + 2 < ntiles) loadKV(kt + 2, (kt + 2) % 3);

        // per 16-col block: S = Q K^T, softmax in registers -> matrix_a frag, O += P V
#pragma unroll
        for (int nt4 = 0; nt4 < 4; nt4++) {
            wmma::fragment<wmma::accumulator, 16, 16, 16, float> sacc;
            wmma::fill_fragment(sacc, 0.0f);
#pragma unroll
            for (int kk = 0; kk < 4; kk++) {
                wmma::fragment<wmma::matrix_b, 16, 16, 16, __half, wmma::col_major> fbh;
                wmma::load_matrix_sync(fbh, skh + (nt4 * 16) * 72 + kk * 16, 72);
                wmma::mma_sync(sacc, fq[kk], fbh, sacc);
            }

            wmma::fragment<wmma::matrix_a, 16, 16, 16, __half, wmma::row_major> fp;
#pragma unroll
            for (int i2 = 0; i2 < 4; i2++) {
                const int i = 2 * i2;
                float s0 = sacc.x[i], s1 = sacc.x[i + 1];
                if (needMask) {
                    const int qg = qglow + ((i & 2) ? 8 : 0);
                    const int kg = k0 + nt4 * 16 + (lane & 3) * 2 + ((i & 4) ? 8 : 0);
                    if (kg     > qg) s0 = -INFINITY;
                    if (kg + 1 > qg) s1 = -INFINITY;
                }
                const __half2 hp = h2exp2(__floats2half2_rn(s0, s1));
                fp.x[i]     = __low2half(hp);
                fp.x[i + 1] = __high2half(hp);
                const float2 lf = __half22float2(hp);
                if (i & 2) lacc1 += lf.x + lf.y; else lacc0 += lf.x + lf.y;
            }

#pragma unroll
            for (int d4 = 0; d4 < 4; d4++) {
                wmma::fragment<wmma::matrix_b, 16, 16, 16, __half, wmma::row_major> fvh;
                wmma::load_matrix_sync(fvh, svh + (nt4 * 16) * 72 + d4 * 16, 72);
                wmma::mma_sync(oacc[d4], fp, fvh, oacc[d4]);
            }
        }
    }

    lacc0 += __shfl_xor_sync(0xffffffffu, lacc0, 1);
    lacc0 += __shfl_xor_sync(0xffffffffu, lacc0, 2);
    lacc1 += __shfl_xor_sync(0xffffffffu, lacc1, 1);
    lacc1 += __shfl_xor_sync(0xffffffffu, lacc1, 2);
    const float inv0 = 1.f / lacc0;
    const float inv1 = 1.f / lacc1;

    const int b = bh >> 4, h = bh & 15;
#pragma unroll
    for (int d4 = 0; d4 < 4; d4++) {
#pragma unroll
        for (int i2 = 0; i2 < 4; i2++) {
            const int i = 2 * i2;
            const int qg   = qglow + ((i & 2) ? 8 : 0);
            const float inv = (i & 2) ? inv1 : inv0;
            const int colb = d4 * 16 + (lane & 3) * 2 + ((i & 4) ? 8 : 0);
            const float v0 = oacc[d4].x[i]     * inv;
            const float v1 = oacc[d4].x[i + 1] * inv;
            const size_t o = ((size_t)(b * kSeq + qg)) * kEmbed + h * kHeadDim + colb;
            *(__half2*)(g_at + o) = __floats2half2_rn(v0, v1);
        }
    }
}

// ======================= launch =======================
extern "C" void kernel_launch(void* const* d_in, const int* in_sizes, int n_in,
                              void* d_out, int out_size) {
    const float* x  = (const float*)d_in[0];
    const float* Wq = (const float*)d_in[1];
    const float* Wk = (const float*)d_in[2];
    const float* Wv = (const float*)d_in[3];
    const float* bq = (const float*)d_in[4];
    const float* bk = (const float*)d_in[5];
    const float* bv = (const float*)d_in[6];
    const float* Wp = (const float*)d_in[7];
    const float* bp = (const float*)d_in[8];
    float* out = (float*)d_out;

    cudaFuncSetAttribute(gemm_wmma_kernel, cudaFuncAttributeMaxDynamicSharedMemorySize, kGemmSmem);
    cudaFuncSetAttribute(attn_wmma_kernel, cudaFuncAttributeMaxDynamicSharedMemorySize, kAttnSmem);

    // fused input/weight conversion + packing
    pack_all_kernel<<<(kCvt3 + 255) / 256, 256>>>(x, Wp, Wq, Wk, Wv, bq, bk, bv);

    // QKV projection: [8192,1024] x [1024,3072] -> fp16 q/k/v
    gemm_wmma_kernel<<<dim3(kQkvN / 128, kRows / 128), 128, kGemmSmem>>>(nullptr, nullptr, 0);

    // causal attention on tensor cores
    attn_wmma_kernel<<<dim3(kSeq / 128, kBatch * kHeads), 256, kAttnSmem>>>();

    // output projection: [8192,1024] x [1024,1024] + bias
    gemm_wmma_kernel<<<dim3(kEmbed / 128, kRows / 128), 128, kGemmSmem>>>(bp, out, 1);
}